// round 1
// baseline (speedup 1.0000x reference)
#include <cuda_runtime.h>
#include <math.h>

// Problem constants
#define BB   32
#define SS   512
#define DD   512
#define HH   8
#define DKK  64
#define FFD  2048
#define NBLK 2
#define MTOK (BB*SS)            // 16384 token rows
#define BSD  (BB*SS*DD)         // 8388608
#define BSF  (BB*SS*FFD)        // 33554432

// Scratch (static device globals — no allocation allowed)
__device__ float g_x[BSD];
__device__ float g_y[BSD];
__device__ float g_q[BSD];
__device__ float g_v[BSD];
__device__ float g_t[BSD];
__device__ float g_ff[BSF];

// ---------------------------------------------------------------------------
// x = q_embed + pe ; y = qa_embed + pe    (pe broadcast over batch)
// ---------------------------------------------------------------------------
__global__ void add_pe_kernel(const float4* __restrict__ qe,
                              const float4* __restrict__ qa,
                              const float4* __restrict__ pe,
                              float4* __restrict__ x,
                              float4* __restrict__ y)
{
    int i = blockIdx.x * blockDim.x + threadIdx.x;
    const int n4 = BSD / 4;
    if (i >= n4) return;
    int pi = i & (SS * DD / 4 - 1);   // S*D/4 = 65536 (pow2)
    float4 p = pe[pi];
    float4 a = qe[i];
    a.x += p.x; a.y += p.y; a.z += p.z; a.w += p.w;
    x[i] = a;
    float4 b = qa[i];
    b.x += p.x; b.y += p.y; b.z += p.z; b.w += p.w;
    y[i] = b;
}

// ---------------------------------------------------------------------------
// C[M,N] = A[M,K] @ W[K,N] + bias[N]   (optional ReLU)
// 128x128 tile, BK=8, 256 threads, 8x8 micro-tile per thread.
// Requires M%128==0, N%128==0, K%8==0 (true for all shapes here).
// ---------------------------------------------------------------------------
template<bool RELU>
__global__ void __launch_bounds__(256) sgemm_bias_kernel(
    const float* __restrict__ A, const float* __restrict__ W,
    const float* __restrict__ bias, float* __restrict__ C,
    int M, int N, int K)
{
    __shared__ float As[8][132];   // padded stride to kill STS bank conflicts
    __shared__ float Bs[8][128];

    const int tid = threadIdx.x;
    const int m0 = blockIdx.y * 128;
    const int n0 = blockIdx.x * 128;
    const int tx = tid & 15;       // 0..15 -> N micro
    const int ty = tid >> 4;       // 0..15 -> M micro
    const int arow = tid >> 1;             // 0..127
    const int acol = (tid & 1) << 2;       // 0 or 4
    const int brow = tid >> 5;             // 0..7
    const int bcol = (tid & 31) << 2;      // 0..124

    const float* Aptr = A + (size_t)(m0 + arow) * K + acol;
    const float* Wptr = W + (size_t)brow * N + n0 + bcol;

    float acc[8][8];
#pragma unroll
    for (int i = 0; i < 8; i++)
#pragma unroll
        for (int j = 0; j < 8; j++) acc[i][j] = 0.f;

    for (int k0 = 0; k0 < K; k0 += 8) {
        float4 av = *(const float4*)(Aptr + k0);
        As[acol + 0][arow] = av.x;
        As[acol + 1][arow] = av.y;
        As[acol + 2][arow] = av.z;
        As[acol + 3][arow] = av.w;
        float4 bv = *(const float4*)(Wptr + (size_t)k0 * N);
        *(float4*)&Bs[brow][bcol] = bv;
        __syncthreads();

#pragma unroll
        for (int k = 0; k < 8; k++) {
            float ra[8], rb[8];
            *(float4*)(ra)     = *(const float4*)&As[k][ty * 8];
            *(float4*)(ra + 4) = *(const float4*)&As[k][ty * 8 + 4];
            *(float4*)(rb)     = *(const float4*)&Bs[k][tx * 8];
            *(float4*)(rb + 4) = *(const float4*)&Bs[k][tx * 8 + 4];
#pragma unroll
            for (int i = 0; i < 8; i++)
#pragma unroll
                for (int j = 0; j < 8; j++)
                    acc[i][j] = fmaf(ra[i], rb[j], acc[i][j]);
        }
        __syncthreads();
    }

#pragma unroll
    for (int i = 0; i < 8; i++) {
        size_t row = (size_t)(m0 + ty * 8 + i);
        float* cp = C + row * N + n0 + tx * 8;
#pragma unroll
        for (int j = 0; j < 8; j++) {
            float v = acc[i][j] + bias[n0 + tx * 8 + j];
            if (RELU) v = fmaxf(v, 0.f);
            cp[j] = v;
        }
    }
}

// ---------------------------------------------------------------------------
// Flash attention, q==k (kq_same), scores scaled by forget_rate[b,i]/sqrt(dk),
// strict-causal mask (j < i), attn row 0 forced to zero.
// Grid: (S/64, B*H). 256 threads. Dynamic smem: 3 * 64*68 floats.
// Q,V layout: [B, S, D] with head h occupying columns h*64..h*64+63.
// Out: same layout.
// ---------------------------------------------------------------------------
#define ATTN_PAD 68
#define ATTN_SMEM (3 * 64 * ATTN_PAD * sizeof(float))

__global__ void __launch_bounds__(256) attn_kernel(
    const float* __restrict__ Q, const float* __restrict__ V,
    const float* __restrict__ FR, float* __restrict__ Out)
{
    extern __shared__ float sm[];
    float* Qs  = sm;                       // 64 x 68 (q tile)
    float* KPs = sm + 64 * ATTN_PAD;       // 64 x 68 (k tile, then p tile)
    float* Vs  = sm + 2 * 64 * ATTN_PAD;   // 64 x 68 (v tile)

    const int qt  = blockIdx.x;            // q-row tile
    const int bh  = blockIdx.y;
    const int b   = bh >> 3;
    const int h   = bh & 7;
    const int tid = threadIdx.x;
    const int r0  = (tid >> 4) << 2;       // 0..60 (row micro base)
    const int c0  = (tid & 15) << 2;       // 0..60 (col micro base)
    const int q0  = qt * 64;
    const size_t base = (size_t)b * SS * DD + (size_t)h * DKK;

    // load Q tile
    {
        int rr = tid >> 2;
        int d0 = (tid & 3) << 4;
        const float4* src = (const float4*)(Q + base + (size_t)(q0 + rr) * DD + d0);
        float4* dst = (float4*)(Qs + rr * ATTN_PAD + d0);
#pragma unroll
        for (int j = 0; j < 4; j++) dst[j] = src[j];
    }

    float frs[4];
#pragma unroll
    for (int i = 0; i < 4; i++)
        frs[i] = FR[b * SS + q0 + r0 + i] * 0.125f;   // 1/sqrt(64)

    float m[4], l[4], o[4][4];
#pragma unroll
    for (int i = 0; i < 4; i++) {
        m[i] = -3.0e38f; l[i] = 0.f;
#pragma unroll
        for (int j = 0; j < 4; j++) o[i][j] = 0.f;
    }

    for (int kt = 0; kt <= qt; kt++) {
        __syncthreads();   // previous iter's GEMM2 done (also covers Q-load)
        {
            int rr = tid >> 2;
            int d0 = (tid & 3) << 4;
            const float4* ks = (const float4*)(Q + base + (size_t)(kt * 64 + rr) * DD + d0);
            const float4* vs = (const float4*)(V + base + (size_t)(kt * 64 + rr) * DD + d0);
            float4* kd = (float4*)(KPs + rr * ATTN_PAD + d0);
            float4* vd = (float4*)(Vs  + rr * ATTN_PAD + d0);
#pragma unroll
            for (int j = 0; j < 4; j++) { kd[j] = ks[j]; vd[j] = vs[j]; }
        }
        __syncthreads();

        // GEMM1: s = Q Q^T  (k == q)
        float s[4][4];
#pragma unroll
        for (int i = 0; i < 4; i++)
#pragma unroll
            for (int j = 0; j < 4; j++) s[i][j] = 0.f;

#pragma unroll
        for (int d = 0; d < 64; d += 4) {
            float4 qv[4], kv[4];
#pragma unroll
            for (int i = 0; i < 4; i++) qv[i] = *(const float4*)(Qs  + (r0 + i) * ATTN_PAD + d);
#pragma unroll
            for (int j = 0; j < 4; j++) kv[j] = *(const float4*)(KPs + (c0 + j) * ATTN_PAD + d);
#pragma unroll
            for (int i = 0; i < 4; i++)
#pragma unroll
                for (int j = 0; j < 4; j++)
                    s[i][j] += qv[i].x * kv[j].x + qv[i].y * kv[j].y +
                               qv[i].z * kv[j].z + qv[i].w * kv[j].w;
        }

        const bool diag = (kt == qt);
        float p[4][4];
#pragma unroll
        for (int i = 0; i < 4; i++) {
            float rmax = -3.0e38f;
#pragma unroll
            for (int j = 0; j < 4; j++) {
                float sv = s[i][j] * frs[i];
                if (diag && (c0 + j) >= (r0 + i)) sv = -1e30f;  // mask j >= i
                s[i][j] = sv;
                rmax = fmaxf(rmax, sv);
            }
#pragma unroll
            for (int ofs = 1; ofs < 16; ofs <<= 1)
                rmax = fmaxf(rmax, __shfl_xor_sync(0xffffffffu, rmax, ofs));
            float mn = fmaxf(m[i], rmax);
            float alpha = __expf(m[i] - mn);
            m[i] = mn;
            float su = 0.f;
#pragma unroll
            for (int j = 0; j < 4; j++) {
                float pv = __expf(s[i][j] - mn);
                p[i][j] = pv;
                su += pv;
            }
#pragma unroll
            for (int ofs = 1; ofs < 16; ofs <<= 1)
                su += __shfl_xor_sync(0xffffffffu, su, ofs);
            l[i] = l[i] * alpha + su;
#pragma unroll
            for (int j = 0; j < 4; j++) o[i][j] *= alpha;
        }

        __syncthreads();   // GEMM1 reads of KPs done before overwriting with P
#pragma unroll
        for (int i = 0; i < 4; i++)
#pragma unroll
            for (int j = 0; j < 4; j++)
                KPs[(r0 + i) * ATTN_PAD + c0 + j] = p[i][j];
        __syncthreads();

        // GEMM2: o += P V
#pragma unroll
        for (int k = 0; k < 64; k += 4) {
            float4 pv[4], vv[4];
#pragma unroll
            for (int i = 0; i < 4; i++) pv[i] = *(const float4*)(KPs + (r0 + i) * ATTN_PAD + k);
#pragma unroll
            for (int kk = 0; kk < 4; kk++) vv[kk] = *(const float4*)(Vs + (k + kk) * ATTN_PAD + c0);
#pragma unroll
            for (int i = 0; i < 4; i++) {
                o[i][0] += pv[i].x * vv[0].x + pv[i].y * vv[1].x + pv[i].z * vv[2].x + pv[i].w * vv[3].x;
                o[i][1] += pv[i].x * vv[0].y + pv[i].y * vv[1].y + pv[i].z * vv[2].y + pv[i].w * vv[3].y;
                o[i][2] += pv[i].x * vv[0].z + pv[i].y * vv[1].z + pv[i].z * vv[2].z + pv[i].w * vv[3].z;
                o[i][3] += pv[i].x * vv[0].w + pv[i].y * vv[1].w + pv[i].z * vv[2].w + pv[i].w * vv[3].w;
            }
        }
    }

#pragma unroll
    for (int i = 0; i < 4; i++) {
        int gi = q0 + r0 + i;
        float inv = (gi == 0) ? 0.f : (1.0f / l[i]);   // zero_pad row 0
        float* op = Out + base + (size_t)gi * DD + c0;
        op[0] = o[i][0] * inv;
        op[1] = o[i][1] * inv;
        op[2] = o[i][2] * inv;
        op[3] = o[i][3] * inv;
    }
}

// ---------------------------------------------------------------------------
// out[row] = LayerNorm(x[row] + r[row]) * g + be       (D = 512, 128 threads)
// ---------------------------------------------------------------------------
__global__ void __launch_bounds__(128) ln_res_kernel(
    const float* __restrict__ x, const float* __restrict__ r,
    const float* __restrict__ g, const float* __restrict__ be,
    float* __restrict__ out)
{
    int row = blockIdx.x;
    int tid = threadIdx.x;
    const float4* xp = (const float4*)(x + (size_t)row * DD);
    const float4* rp = (const float4*)(r + (size_t)row * DD);
    float4 v = xp[tid], w = rp[tid];
    v.x += w.x; v.y += w.y; v.z += w.z; v.w += w.w;
    float s  = v.x + v.y + v.z + v.w;
    float ss = v.x * v.x + v.y * v.y + v.z * v.z + v.w * v.w;
#pragma unroll
    for (int ofs = 16; ofs > 0; ofs >>= 1) {
        s  += __shfl_xor_sync(0xffffffffu, s,  ofs);
        ss += __shfl_xor_sync(0xffffffffu, ss, ofs);
    }
    __shared__ float sb[4], ssb[4];
    int wid = tid >> 5;
    if ((tid & 31) == 0) { sb[wid] = s; ssb[wid] = ss; }
    __syncthreads();
    s  = sb[0]  + sb[1]  + sb[2]  + sb[3];
    ss = ssb[0] + ssb[1] + ssb[2] + ssb[3];
    float mean = s * (1.0f / DD);
    float var  = ss * (1.0f / DD) - mean * mean;
    float rs   = rsqrtf(var + 1e-5f);
    float4 gv = ((const float4*)g)[tid];
    float4 bv = ((const float4*)be)[tid];
    float4 o4;
    o4.x = (v.x - mean) * rs * gv.x + bv.x;
    o4.y = (v.y - mean) * rs * gv.y + bv.y;
    o4.z = (v.z - mean) * rs * gv.z + bv.z;
    o4.w = (v.w - mean) * rs * gv.w + bv.w;
    ((float4*)(out + (size_t)row * DD))[tid] = o4;
}

// ---------------------------------------------------------------------------
extern "C" void kernel_launch(void* const* d_in, const int* in_sizes, int n_in,
                              void* d_out, int out_size)
{
    const float* qe  = (const float*)d_in[0];
    const float* qa  = (const float*)d_in[1];
    const float* fr  = (const float*)d_in[2];
    const float* pe  = (const float*)d_in[3];
    const float* Wk  = (const float*)d_in[4];
    const float* bk  = (const float*)d_in[5];
    const float* Wv  = (const float*)d_in[6];
    const float* bv  = (const float*)d_in[7];
    const float* Wo  = (const float*)d_in[8];
    const float* bo  = (const float*)d_in[9];
    const float* g1  = (const float*)d_in[10];
    const float* be1 = (const float*)d_in[11];
    const float* W1  = (const float*)d_in[12];
    const float* bf1 = (const float*)d_in[13];
    const float* W2  = (const float*)d_in[14];
    const float* bf2 = (const float*)d_in[15];
    const float* g2  = (const float*)d_in[16];
    const float* be2 = (const float*)d_in[17];
    float* out = (float*)d_out;

    float *px, *py, *pq, *pv, *pt, *pff;
    cudaGetSymbolAddress((void**)&px,  g_x);
    cudaGetSymbolAddress((void**)&py,  g_y);
    cudaGetSymbolAddress((void**)&pq,  g_q);
    cudaGetSymbolAddress((void**)&pv,  g_v);
    cudaGetSymbolAddress((void**)&pt,  g_t);
    cudaGetSymbolAddress((void**)&pff, g_ff);

    cudaFuncSetAttribute(attn_kernel,
                         cudaFuncAttributeMaxDynamicSharedMemorySize,
                         (int)ATTN_SMEM);

    add_pe_kernel<<<(BSD / 4 + 255) / 256, 256>>>(
        (const float4*)qe, (const float4*)qa, (const float4*)pe,
        (float4*)px, (float4*)py);

    dim3 g512(DD / 128, MTOK / 128);    // (4, 128)
    dim3 gff(FFD / 128, MTOK / 128);    // (16, 128)
    dim3 gattn(SS / 64, BB * HH);       // (8, 256)

    for (int i = 0; i < NBLK; i++) {
        const float* Wki = Wk + (size_t)i * DD * DD;
        const float* Wvi = Wv + (size_t)i * DD * DD;
        const float* Woi = Wo + (size_t)i * DD * DD;
        const float* W1i = W1 + (size_t)i * DD * FFD;
        const float* W2i = W2 + (size_t)i * FFD * DD;

        // q = x @ Wk + bk  (q == k since kq_same)
        sgemm_bias_kernel<false><<<g512, 256>>>(px, Wki, bk + i * DD, pq, MTOK, DD, DD);
        // v = y @ Wv + bv
        sgemm_bias_kernel<false><<<g512, 256>>>(py, Wvi, bv + i * DD, pv, MTOK, DD, DD);
        // attention -> pt
        attn_kernel<<<gattn, 256, ATTN_SMEM>>>(pq, pv, fr, pt);
        // attn proj -> pq (reuse)
        sgemm_bias_kernel<false><<<g512, 256>>>(pt, Woi, bo + i * DD, pq, MTOK, DD, DD);
        // x = LN(x + proj)
        ln_res_kernel<<<MTOK, 128>>>(px, pq, g1 + i * DD, be1 + i * DD, px);
        // ffn hidden = relu(x @ W1 + bf1)
        sgemm_bias_kernel<true><<<gff, 256>>>(px, W1i, bf1 + i * FFD, pff, MTOK, FFD, DD);
        // ffn out = hidden @ W2 + bf2 -> pt
        sgemm_bias_kernel<false><<<g512, 256>>>(pff, W2i, bf2 + i * DD, pt, MTOK, DD, FFD);
        // x = LN(x + ffn)
        float* dst = (i == NBLK - 1) ? out : px;
        ln_res_kernel<<<MTOK, 128>>>(px, pt, g2 + i * DD, be2 + i * DD, dst);
    }
}

// round 3
// speedup vs baseline: 1.9304x; 1.9304x over previous
#include <cuda_runtime.h>
#include <math.h>
#include <stdint.h>

// Problem constants
#define BB   32
#define SS   512
#define DD   512
#define HH   8
#define DKK  64
#define FFD  2048
#define NBLK 2
#define MTOK (BB*SS)            // 16384 token rows
#define BSD  (BB*SS*DD)         // 8388608
#define BSF  (BB*SS*FFD)        // 33554432

// Scratch (static device globals — no allocation allowed)
__device__ float g_x[BSD];
__device__ float g_y[BSD];
__device__ float g_q[BSD];
__device__ float g_v[BSD];
__device__ float g_t[BSD];
__device__ float g_ff[BSF];

// ---------------------------------------------------------------------------
// x = q_embed + pe ; y = qa_embed + pe    (pe broadcast over batch)
// ---------------------------------------------------------------------------
__global__ void add_pe_kernel(const float4* __restrict__ qe,
                              const float4* __restrict__ qa,
                              const float4* __restrict__ pe,
                              float4* __restrict__ x,
                              float4* __restrict__ y)
{
    int i = blockIdx.x * blockDim.x + threadIdx.x;
    const int n4 = BSD / 4;
    if (i >= n4) return;
    int pi = i & (SS * DD / 4 - 1);   // S*D/4 = 65536 (pow2)
    float4 p = pe[pi];
    float4 a = qe[i];
    a.x += p.x; a.y += p.y; a.z += p.z; a.w += p.w;
    x[i] = a;
    float4 b = qa[i];
    b.x += p.x; b.y += p.y; b.z += p.z; b.w += p.w;
    y[i] = b;
}

// ---------------------------------------------------------------------------
// TF32 tensor-core GEMM: C[M,N] = A[M,K] @ W[K,N] + bias[N]  (optional ReLU)
// CTA tile 128x128, BK=32, 256 threads = 8 warps (2x4 warp grid, 64x32 warp
// tiles). mma.sync.aligned.m16n8k8.row.col.f32.tf32.tf32.f32.
// Smem row stride 136 words -> conflict-free fragment loads.
// Requires M%128==0, N%128==0, K%32==0 (true for all shapes here).
// ---------------------------------------------------------------------------
#define SMS 136

__device__ __forceinline__ uint32_t to_tf32(float x) {
    uint32_t y;
    asm("cvt.rna.tf32.f32 %0, %1;" : "=r"(y) : "f"(x));
    return y;
}

__device__ __forceinline__ void mma_tf32(float c[4],
                                         uint32_t a0, uint32_t a1,
                                         uint32_t a2, uint32_t a3,
                                         uint32_t b0, uint32_t b1)
{
    asm volatile(
        "mma.sync.aligned.m16n8k8.row.col.f32.tf32.tf32.f32 "
        "{%0,%1,%2,%3}, {%4,%5,%6,%7}, {%8,%9}, {%0,%1,%2,%3};"
        : "+f"(c[0]), "+f"(c[1]), "+f"(c[2]), "+f"(c[3])
        : "r"(a0), "r"(a1), "r"(a2), "r"(a3), "r"(b0), "r"(b1));
}

template<bool RELU>
__global__ void __launch_bounds__(256, 2) tf32_gemm_kernel(
    const float* __restrict__ A, const float* __restrict__ W,
    const float* __restrict__ bias, float* __restrict__ C,
    int M, int N, int K)
{
    __shared__ uint32_t As[32][SMS];   // [k][m] tf32 bit patterns
    __shared__ uint32_t Bs[32][SMS];   // [k][n]

    const int tid   = threadIdx.x;
    const int lane  = tid & 31;
    const int wid   = tid >> 5;
    const int wm    = wid & 1;          // warp m-index (0..1)
    const int wn    = wid >> 1;         // warp n-index (0..3)
    const int grp   = lane >> 2;        // groupID 0..7
    const int tig   = lane & 3;         // threadID_in_group 0..3
    const int m0    = blockIdx.y * 128;
    const int n0    = blockIdx.x * 128;

    float acc[4][4][4];
#pragma unroll
    for (int i = 0; i < 4; i++)
#pragma unroll
        for (int j = 0; j < 4; j++)
#pragma unroll
            for (int r = 0; r < 4; r++) acc[i][j][r] = 0.f;

    const int a_row4 = tid >> 3;        // 0..31
    const int a_c4   = tid & 7;         // 0..7 -> k offset *4

    for (int k0 = 0; k0 < K; k0 += 32) {
        // Load A tile: 128 rows x 32 k. 256 threads x 4 iters x float4.
#pragma unroll
        for (int it = 0; it < 4; it++) {
            int row = a_row4 + it * 32;           // 0..127
            const float4 v = *(const float4*)(A + (size_t)(m0 + row) * K + k0 + a_c4 * 4);
            int kk = a_c4 * 4;
            As[kk + 0][row] = to_tf32(v.x);
            As[kk + 1][row] = to_tf32(v.y);
            As[kk + 2][row] = to_tf32(v.z);
            As[kk + 3][row] = to_tf32(v.w);
        }
        // Load B tile: 32 k rows x 128 n.
#pragma unroll
        for (int it = 0; it < 4; it++) {
            int idx = tid + it * 256;
            int row = idx >> 5;                    // 0..31
            int c4  = idx & 31;                    // 0..31
            const float4 v = *(const float4*)(W + (size_t)(k0 + row) * N + n0 + c4 * 4);
            uint4 t;
            t.x = to_tf32(v.x); t.y = to_tf32(v.y);
            t.z = to_tf32(v.z); t.w = to_tf32(v.w);
            *(uint4*)&Bs[row][c4 * 4] = t;
        }
        __syncthreads();

#pragma unroll
        for (int kk = 0; kk < 32; kk += 8) {
            uint32_t af[4][4];
            uint32_t bf[4][2];
#pragma unroll
            for (int mt = 0; mt < 4; mt++) {
                int mr = wm * 64 + mt * 16 + grp;
                af[mt][0] = As[kk + tig    ][mr    ];
                af[mt][1] = As[kk + tig    ][mr + 8];
                af[mt][2] = As[kk + tig + 4][mr    ];
                af[mt][3] = As[kk + tig + 4][mr + 8];
            }
#pragma unroll
            for (int nt = 0; nt < 4; nt++) {
                int nc = wn * 32 + nt * 8 + grp;
                bf[nt][0] = Bs[kk + tig    ][nc];
                bf[nt][1] = Bs[kk + tig + 4][nc];
            }
#pragma unroll
            for (int mt = 0; mt < 4; mt++)
#pragma unroll
                for (int nt = 0; nt < 4; nt++)
                    mma_tf32(acc[mt][nt],
                             af[mt][0], af[mt][1], af[mt][2], af[mt][3],
                             bf[nt][0], bf[nt][1]);
        }
        __syncthreads();
    }

    // Epilogue: bias (+ReLU), write float2 pairs
#pragma unroll
    for (int mt = 0; mt < 4; mt++) {
#pragma unroll
        for (int nt = 0; nt < 4; nt++) {
            int row = m0 + wm * 64 + mt * 16 + grp;
            int col = n0 + wn * 32 + nt * 8 + tig * 2;
            float b0 = bias[col], b1 = bias[col + 1];
            float v0 = acc[mt][nt][0] + b0;
            float v1 = acc[mt][nt][1] + b1;
            float v2 = acc[mt][nt][2] + b0;
            float v3 = acc[mt][nt][3] + b1;
            if (RELU) {
                v0 = fmaxf(v0, 0.f); v1 = fmaxf(v1, 0.f);
                v2 = fmaxf(v2, 0.f); v3 = fmaxf(v3, 0.f);
            }
            *(float2*)(C + (size_t)row * N + col)       = make_float2(v0, v1);
            *(float2*)(C + (size_t)(row + 8) * N + col) = make_float2(v2, v3);
        }
    }
}

// ---------------------------------------------------------------------------
// Flash attention, q==k (kq_same), scores scaled by forget_rate[b,i]/sqrt(dk),
// strict-causal mask (j < i), attn row 0 forced to zero.
// Grid: (S/64, B*H). 256 threads. Dynamic smem: 3 * 64*68 floats.
// ---------------------------------------------------------------------------
#define ATTN_PAD 68
#define ATTN_SMEM (3 * 64 * ATTN_PAD * sizeof(float))

__global__ void __launch_bounds__(256) attn_kernel(
    const float* __restrict__ Q, const float* __restrict__ V,
    const float* __restrict__ FR, float* __restrict__ Out)
{
    extern __shared__ float sm[];
    float* Qs  = sm;                       // 64 x 68 (q tile)
    float* KPs = sm + 64 * ATTN_PAD;       // 64 x 68 (k tile, then p tile)
    float* Vs  = sm + 2 * 64 * ATTN_PAD;   // 64 x 68 (v tile)

    const int qt  = blockIdx.x;            // q-row tile
    const int bh  = blockIdx.y;
    const int b   = bh >> 3;
    const int h   = bh & 7;
    const int tid = threadIdx.x;
    const int r0  = (tid >> 4) << 2;       // 0..60 (row micro base)
    const int c0  = (tid & 15) << 2;       // 0..60 (col micro base)
    const int q0  = qt * 64;
    const size_t base = (size_t)b * SS * DD + (size_t)h * DKK;

    // load Q tile
    {
        int rr = tid >> 2;
        int d0 = (tid & 3) << 4;
        const float4* src = (const float4*)(Q + base + (size_t)(q0 + rr) * DD + d0);
        float4* dst = (float4*)(Qs + rr * ATTN_PAD + d0);
#pragma unroll
        for (int j = 0; j < 4; j++) dst[j] = src[j];
    }

    float frs[4];
#pragma unroll
    for (int i = 0; i < 4; i++)
        frs[i] = FR[b * SS + q0 + r0 + i] * 0.125f;   // 1/sqrt(64)

    float m[4], l[4], o[4][4];
#pragma unroll
    for (int i = 0; i < 4; i++) {
        m[i] = -3.0e38f; l[i] = 0.f;
#pragma unroll
        for (int j = 0; j < 4; j++) o[i][j] = 0.f;
    }

    for (int kt = 0; kt <= qt; kt++) {
        __syncthreads();   // previous iter's GEMM2 done (also covers Q-load)
        {
            int rr = tid >> 2;
            int d0 = (tid & 3) << 4;
            const float4* ks = (const float4*)(Q + base + (size_t)(kt * 64 + rr) * DD + d0);
            const float4* vs = (const float4*)(V + base + (size_t)(kt * 64 + rr) * DD + d0);
            float4* kd = (float4*)(KPs + rr * ATTN_PAD + d0);
            float4* vd = (float4*)(Vs  + rr * ATTN_PAD + d0);
#pragma unroll
            for (int j = 0; j < 4; j++) { kd[j] = ks[j]; vd[j] = vs[j]; }
        }
        __syncthreads();

        // GEMM1: s = Q Q^T  (k == q)
        float s[4][4];
#pragma unroll
        for (int i = 0; i < 4; i++)
#pragma unroll
            for (int j = 0; j < 4; j++) s[i][j] = 0.f;

#pragma unroll
        for (int d = 0; d < 64; d += 4) {
            float4 qv[4], kv[4];
#pragma unroll
            for (int i = 0; i < 4; i++) qv[i] = *(const float4*)(Qs  + (r0 + i) * ATTN_PAD + d);
#pragma unroll
            for (int j = 0; j < 4; j++) kv[j] = *(const float4*)(KPs + (c0 + j) * ATTN_PAD + d);
#pragma unroll
            for (int i = 0; i < 4; i++)
#pragma unroll
                for (int j = 0; j < 4; j++)
                    s[i][j] += qv[i].x * kv[j].x + qv[i].y * kv[j].y +
                               qv[i].z * kv[j].z + qv[i].w * kv[j].w;
        }

        const bool diag = (kt == qt);
        float p[4][4];
#pragma unroll
        for (int i = 0; i < 4; i++) {
            float rmax = -3.0e38f;
#pragma unroll
            for (int j = 0; j < 4; j++) {
                float sv = s[i][j] * frs[i];
                if (diag && (c0 + j) >= (r0 + i)) sv = -1e30f;  // mask j >= i
                s[i][j] = sv;
                rmax = fmaxf(rmax, sv);
            }
#pragma unroll
            for (int ofs = 1; ofs < 16; ofs <<= 1)
                rmax = fmaxf(rmax, __shfl_xor_sync(0xffffffffu, rmax, ofs));
            float mn = fmaxf(m[i], rmax);
            float alpha = __expf(m[i] - mn);
            m[i] = mn;
            float su = 0.f;
#pragma unroll
            for (int j = 0; j < 4; j++) {
                float pv = __expf(s[i][j] - mn);
                p[i][j] = pv;
                su += pv;
            }
#pragma unroll
            for (int ofs = 1; ofs < 16; ofs <<= 1)
                su += __shfl_xor_sync(0xffffffffu, su, ofs);
            l[i] = l[i] * alpha + su;
#pragma unroll
            for (int j = 0; j < 4; j++) o[i][j] *= alpha;
        }

        __syncthreads();   // GEMM1 reads of KPs done before overwriting with P
#pragma unroll
        for (int i = 0; i < 4; i++)
#pragma unroll
            for (int j = 0; j < 4; j++)
                KPs[(r0 + i) * ATTN_PAD + c0 + j] = p[i][j];
        __syncthreads();

        // GEMM2: o += P V
#pragma unroll
        for (int k = 0; k < 64; k += 4) {
            float4 pv[4], vv[4];
#pragma unroll
            for (int i = 0; i < 4; i++) pv[i] = *(const float4*)(KPs + (r0 + i) * ATTN_PAD + k);
#pragma unroll
            for (int kk = 0; kk < 4; kk++) vv[kk] = *(const float4*)(Vs + (k + kk) * ATTN_PAD + c0);
#pragma unroll
            for (int i = 0; i < 4; i++) {
                o[i][0] += pv[i].x * vv[0].x + pv[i].y * vv[1].x + pv[i].z * vv[2].x + pv[i].w * vv[3].x;
                o[i][1] += pv[i].x * vv[0].y + pv[i].y * vv[1].y + pv[i].z * vv[2].y + pv[i].w * vv[3].y;
                o[i][2] += pv[i].x * vv[0].z + pv[i].y * vv[1].z + pv[i].z * vv[2].z + pv[i].w * vv[3].z;
                o[i][3] += pv[i].x * vv[0].w + pv[i].y * vv[1].w + pv[i].z * vv[2].w + pv[i].w * vv[3].w;
            }
        }
    }

#pragma unroll
    for (int i = 0; i < 4; i++) {
        int gi = q0 + r0 + i;
        float inv = (gi == 0) ? 0.f : (1.0f / l[i]);   // zero_pad row 0
        float* op = Out + base + (size_t)gi * DD + c0;
        op[0] = o[i][0] * inv;
        op[1] = o[i][1] * inv;
        op[2] = o[i][2] * inv;
        op[3] = o[i][3] * inv;
    }
}

// ---------------------------------------------------------------------------
// out[row] = LayerNorm(x[row] + r[row]) * g + be       (D = 512, 128 threads)
// ---------------------------------------------------------------------------
__global__ void __launch_bounds__(128) ln_res_kernel(
    const float* __restrict__ x, const float* __restrict__ r,
    const float* __restrict__ g, const float* __restrict__ be,
    float* __restrict__ out)
{
    int row = blockIdx.x;
    int tid = threadIdx.x;
    const float4* xp = (const float4*)(x + (size_t)row * DD);
    const float4* rp = (const float4*)(r + (size_t)row * DD);
    float4 v = xp[tid], w = rp[tid];
    v.x += w.x; v.y += w.y; v.z += w.z; v.w += w.w;
    float s  = v.x + v.y + v.z + v.w;
    float ss = v.x * v.x + v.y * v.y + v.z * v.z + v.w * v.w;
#pragma unroll
    for (int ofs = 16; ofs > 0; ofs >>= 1) {
        s  += __shfl_xor_sync(0xffffffffu, s,  ofs);
        ss += __shfl_xor_sync(0xffffffffu, ss, ofs);
    }
    __shared__ float sb[4], ssb[4];
    int wid = tid >> 5;
    if ((tid & 31) == 0) { sb[wid] = s; ssb[wid] = ss; }
    __syncthreads();
    s  = sb[0]  + sb[1]  + sb[2]  + sb[3];
    ss = ssb[0] + ssb[1] + ssb[2] + ssb[3];
    float mean = s * (1.0f / DD);
    float var  = ss * (1.0f / DD) - mean * mean;
    float rs   = rsqrtf(var + 1e-5f);
    float4 gv = ((const float4*)g)[tid];
    float4 bv = ((const float4*)be)[tid];
    float4 o4;
    o4.x = (v.x - mean) * rs * gv.x + bv.x;
    o4.y = (v.y - mean) * rs * gv.y + bv.y;
    o4.z = (v.z - mean) * rs * gv.z + bv.z;
    o4.w = (v.w - mean) * rs * gv.w + bv.w;
    ((float4*)(out + (size_t)row * DD))[tid] = o4;
}

// ---------------------------------------------------------------------------
extern "C" void kernel_launch(void* const* d_in, const int* in_sizes, int n_in,
                              void* d_out, int out_size)
{
    const float* qe  = (const float*)d_in[0];
    const float* qa  = (const float*)d_in[1];
    const float* fr  = (const float*)d_in[2];
    const float* pe  = (const float*)d_in[3];
    const float* Wk  = (const float*)d_in[4];
    const float* bk  = (const float*)d_in[5];
    const float* Wv  = (const float*)d_in[6];
    const float* bv  = (const float*)d_in[7];
    const float* Wo  = (const float*)d_in[8];
    const float* bo  = (const float*)d_in[9];
    const float* g1  = (const float*)d_in[10];
    const float* be1 = (const float*)d_in[11];
    const float* W1  = (const float*)d_in[12];
    const float* bf1 = (const float*)d_in[13];
    const float* W2  = (const float*)d_in[14];
    const float* bf2 = (const float*)d_in[15];
    const float* g2  = (const float*)d_in[16];
    const float* be2 = (const float*)d_in[17];
    float* out = (float*)d_out;

    float *px, *py, *pq, *pv, *pt, *pff;
    cudaGetSymbolAddress((void**)&px,  g_x);
    cudaGetSymbolAddress((void**)&py,  g_y);
    cudaGetSymbolAddress((void**)&pq,  g_q);
    cudaGetSymbolAddress((void**)&pv,  g_v);
    cudaGetSymbolAddress((void**)&pt,  g_t);
    cudaGetSymbolAddress((void**)&pff, g_ff);

    cudaFuncSetAttribute(attn_kernel,
                         cudaFuncAttributeMaxDynamicSharedMemorySize,
                         (int)ATTN_SMEM);

    add_pe_kernel<<<(BSD / 4 + 255) / 256, 256>>>(
        (const float4*)qe, (const float4*)qa, (const float4*)pe,
        (float4*)px, (float4*)py);

    dim3 g512(DD / 128, MTOK / 128);    // (4, 128)
    dim3 gff(FFD / 128, MTOK / 128);    // (16, 128)
    dim3 gattn(SS / 64, BB * HH);       // (8, 256)

    for (int i = 0; i < NBLK; i++) {
        const float* Wki = Wk + (size_t)i * DD * DD;
        const float* Wvi = Wv + (size_t)i * DD * DD;
        const float* Woi = Wo + (size_t)i * DD * DD;
        const float* W1i = W1 + (size_t)i * DD * FFD;
        const float* W2i = W2 + (size_t)i * FFD * DD;

        // q = x @ Wk + bk  (q == k since kq_same)
        tf32_gemm_kernel<false><<<g512, 256>>>(px, Wki, bk + i * DD, pq, MTOK, DD, DD);
        // v = y @ Wv + bv
        tf32_gemm_kernel<false><<<g512, 256>>>(py, Wvi, bv + i * DD, pv, MTOK, DD, DD);
        // attention -> pt
        attn_kernel<<<gattn, 256, ATTN_SMEM>>>(pq, pv, fr, pt);
        // attn proj -> pq (reuse)
        tf32_gemm_kernel<false><<<g512, 256>>>(pt, Woi, bo + i * DD, pq, MTOK, DD, DD);
        // x = LN(x + proj)
        ln_res_kernel<<<MTOK, 128>>>(px, pq, g1 + i * DD, be1 + i * DD, px);
        // ffn hidden = relu(x @ W1 + bf1)
        tf32_gemm_kernel<true><<<gff, 256>>>(px, W1i, bf1 + i * FFD, pff, MTOK, FFD, DD);
        // ffn out = hidden @ W2 + bf2 -> pt
        tf32_gemm_kernel<false><<<g512, 256>>>(pff, W2i, bf2 + i * DD, pt, MTOK, DD, FFD);
        // x = LN(x + ffn)
        float* dst = (i == NBLK - 1) ? out : px;
        ln_res_kernel<<<MTOK, 128>>>(px, pt, g2 + i * DD, be2 + i * DD, dst);
    }
}

// round 4
// speedup vs baseline: 2.6375x; 1.3663x over previous
#include <cuda_runtime.h>
#include <math.h>
#include <stdint.h>

// Problem constants
#define BB   32
#define SS   512
#define DD   512
#define HH   8
#define DKK  64
#define FFD  2048
#define NBLK 2
#define MTOK (BB*SS)            // 16384 token rows
#define BSD  (BB*SS*DD)         // 8388608
#define BSF  (BB*SS*FFD)        // 33554432

// Scratch (static device globals — no allocation allowed)
__device__ float g_x[BSD];
__device__ float g_y[BSD];
__device__ float g_q[BSD];
__device__ float g_v[BSD];
__device__ float g_t[BSD];
__device__ float g_ff[BSF];

// ---------------------------------------------------------------------------
__global__ void add_pe_kernel(const float4* __restrict__ qe,
                              const float4* __restrict__ qa,
                              const float4* __restrict__ pe,
                              float4* __restrict__ x,
                              float4* __restrict__ y)
{
    int i = blockIdx.x * blockDim.x + threadIdx.x;
    const int n4 = BSD / 4;
    if (i >= n4) return;
    int pi = i & (SS * DD / 4 - 1);
    float4 p = pe[pi];
    float4 a = qe[i];
    a.x += p.x; a.y += p.y; a.z += p.z; a.w += p.w;
    x[i] = a;
    float4 b = qa[i];
    b.x += p.x; b.y += p.y; b.z += p.z; b.w += p.w;
    y[i] = b;
}

// ---------------------------------------------------------------------------
// TF32 helpers
// ---------------------------------------------------------------------------
__device__ __forceinline__ uint32_t to_tf32(float x) {
    uint32_t y;
    asm("cvt.rna.tf32.f32 %0, %1;" : "=r"(y) : "f"(x));
    return y;
}

__device__ __forceinline__ void mma_tf32(float c[4],
                                         uint32_t a0, uint32_t a1,
                                         uint32_t a2, uint32_t a3,
                                         uint32_t b0, uint32_t b1)
{
    asm volatile(
        "mma.sync.aligned.m16n8k8.row.col.f32.tf32.tf32.f32 "
        "{%0,%1,%2,%3}, {%4,%5,%6,%7}, {%8,%9}, {%0,%1,%2,%3};"
        : "+f"(c[0]), "+f"(c[1]), "+f"(c[2]), "+f"(c[3])
        : "r"(a0), "r"(a1), "r"(a2), "r"(a3), "r"(b0), "r"(b1));
}

// ---------------------------------------------------------------------------
// TF32 tensor-core GEMM: C[M,N] = A[M,K] @ W[K,N] + bias[N]  (optional ReLU)
// ---------------------------------------------------------------------------
#define SMS 136

template<bool RELU>
__global__ void __launch_bounds__(256, 2) tf32_gemm_kernel(
    const float* __restrict__ A, const float* __restrict__ W,
    const float* __restrict__ bias, float* __restrict__ C,
    int M, int N, int K)
{
    __shared__ uint32_t As[32][SMS];   // [k][m] tf32 bit patterns
    __shared__ uint32_t Bs[32][SMS];   // [k][n]

    const int tid   = threadIdx.x;
    const int lane  = tid & 31;
    const int wid   = tid >> 5;
    const int wm    = wid & 1;
    const int wn    = wid >> 1;
    const int grp   = lane >> 2;
    const int tig   = lane & 3;
    const int m0    = blockIdx.y * 128;
    const int n0    = blockIdx.x * 128;

    float acc[4][4][4];
#pragma unroll
    for (int i = 0; i < 4; i++)
#pragma unroll
        for (int j = 0; j < 4; j++)
#pragma unroll
            for (int r = 0; r < 4; r++) acc[i][j][r] = 0.f;

    const int a_row4 = tid >> 3;
    const int a_c4   = tid & 7;

    for (int k0 = 0; k0 < K; k0 += 32) {
#pragma unroll
        for (int it = 0; it < 4; it++) {
            int row = a_row4 + it * 32;
            const float4 v = *(const float4*)(A + (size_t)(m0 + row) * K + k0 + a_c4 * 4);
            int kk = a_c4 * 4;
            As[kk + 0][row] = to_tf32(v.x);
            As[kk + 1][row] = to_tf32(v.y);
            As[kk + 2][row] = to_tf32(v.z);
            As[kk + 3][row] = to_tf32(v.w);
        }
#pragma unroll
        for (int it = 0; it < 4; it++) {
            int idx = tid + it * 256;
            int row = idx >> 5;
            int c4  = idx & 31;
            const float4 v = *(const float4*)(W + (size_t)(k0 + row) * N + n0 + c4 * 4);
            uint4 t;
            t.x = to_tf32(v.x); t.y = to_tf32(v.y);
            t.z = to_tf32(v.z); t.w = to_tf32(v.w);
            *(uint4*)&Bs[row][c4 * 4] = t;
        }
        __syncthreads();

#pragma unroll
        for (int kk = 0; kk < 32; kk += 8) {
            uint32_t af[4][4];
            uint32_t bf[4][2];
#pragma unroll
            for (int mt = 0; mt < 4; mt++) {
                int mr = wm * 64 + mt * 16 + grp;
                af[mt][0] = As[kk + tig    ][mr    ];
                af[mt][1] = As[kk + tig    ][mr + 8];
                af[mt][2] = As[kk + tig + 4][mr    ];
                af[mt][3] = As[kk + tig + 4][mr + 8];
            }
#pragma unroll
            for (int nt = 0; nt < 4; nt++) {
                int nc = wn * 32 + nt * 8 + grp;
                bf[nt][0] = Bs[kk + tig    ][nc];
                bf[nt][1] = Bs[kk + tig + 4][nc];
            }
#pragma unroll
            for (int mt = 0; mt < 4; mt++)
#pragma unroll
                for (int nt = 0; nt < 4; nt++)
                    mma_tf32(acc[mt][nt],
                             af[mt][0], af[mt][1], af[mt][2], af[mt][3],
                             bf[nt][0], bf[nt][1]);
        }
        __syncthreads();
    }

#pragma unroll
    for (int mt = 0; mt < 4; mt++) {
#pragma unroll
        for (int nt = 0; nt < 4; nt++) {
            int row = m0 + wm * 64 + mt * 16 + grp;
            int col = n0 + wn * 32 + nt * 8 + tig * 2;
            float b0 = bias[col], b1 = bias[col + 1];
            float v0 = acc[mt][nt][0] + b0;
            float v1 = acc[mt][nt][1] + b1;
            float v2 = acc[mt][nt][2] + b0;
            float v3 = acc[mt][nt][3] + b1;
            if (RELU) {
                v0 = fmaxf(v0, 0.f); v1 = fmaxf(v1, 0.f);
                v2 = fmaxf(v2, 0.f); v3 = fmaxf(v3, 0.f);
            }
            *(float2*)(C + (size_t)row * N + col)       = make_float2(v0, v1);
            *(float2*)(C + (size_t)(row + 8) * N + col) = make_float2(v2, v3);
        }
    }
}

// ---------------------------------------------------------------------------
// TF32 tensor-core flash attention. q==k (kq_same). scores scaled by
// forget_rate[b,row]/8, strict-causal mask (col < row), output row 0 zeroed.
// Grid: (S/64, B*H). 128 threads = 4 warps, each warp owns a 16-row m-tile.
// Smem: Qs[64][68] + Ks[64][68] + Vs[64][72] tf32 words (53248 B, dynamic).
// P fragments converted S->A layout via register shuffles (no smem P tile).
// ---------------------------------------------------------------------------
#define QK_PAD 68
#define V_PAD  72
#define ATTN_SMEM ((2 * 64 * QK_PAD + 64 * V_PAD) * sizeof(uint32_t))

__global__ void __launch_bounds__(128, 4) attn_mma_kernel(
    const float* __restrict__ Q, const float* __restrict__ V,
    const float* __restrict__ FR, float* __restrict__ Out)
{
    extern __shared__ uint32_t smu[];
    uint32_t* Qs = smu;                      // [64][QK_PAD]
    uint32_t* Ks = smu + 64 * QK_PAD;        // [64][QK_PAD]
    uint32_t* Vs = smu + 2 * 64 * QK_PAD;    // [64][V_PAD]

    const int qt   = blockIdx.x;
    const int bh   = blockIdx.y;
    const int b    = bh >> 3;
    const int h    = bh & 7;
    const int tid  = threadIdx.x;
    const int lane = tid & 31;
    const int w    = tid >> 5;
    const int grp  = lane >> 2;
    const int tig  = lane & 3;
    const int q0   = qt * 64;
    const size_t base = (size_t)b * SS * DD + (size_t)h * DKK;

    // Load Q tile (64 rows x 64 dk), tf32-convert into Qs
#pragma unroll
    for (int j = 0; j < 8; j++) {
        int idx = j * 128 + tid;
        int r   = idx >> 4;
        int c4  = (idx & 15) * 4;
        float4 v = *(const float4*)(Q + base + (size_t)(q0 + r) * DD + c4);
        uint32_t* d = Qs + r * QK_PAD + c4;
        d[0] = to_tf32(v.x); d[1] = to_tf32(v.y);
        d[2] = to_tf32(v.z); d[3] = to_tf32(v.w);
    }

    const int rg0 = q0 + w * 16 + grp;      // this thread's first global row
    const float frs0 = FR[b * SS + rg0]     * 0.125f;
    const float frs1 = FR[b * SS + rg0 + 8] * 0.125f;

    float m0 = -3.0e38f, m1 = -3.0e38f, l0 = 0.f, l1 = 0.f;
    float o[8][4];
#pragma unroll
    for (int nt = 0; nt < 8; nt++)
#pragma unroll
        for (int r = 0; r < 4; r++) o[nt][r] = 0.f;

    for (int kt = 0; kt <= qt; kt++) {
        __syncthreads();   // prior iter's mmas done reading Ks/Vs
#pragma unroll
        for (int j = 0; j < 8; j++) {
            int idx = j * 128 + tid;
            int r   = idx >> 4;
            int c4  = (idx & 15) * 4;
            const float* gk = Q + base + (size_t)(kt * 64 + r) * DD + c4;
            const float* gv = V + base + (size_t)(kt * 64 + r) * DD + c4;
            float4 kv = *(const float4*)gk;
            float4 vv = *(const float4*)gv;
            uint32_t* kd = Ks + r * QK_PAD + c4;
            uint32_t* vd = Vs + r * V_PAD  + c4;
            kd[0] = to_tf32(kv.x); kd[1] = to_tf32(kv.y);
            kd[2] = to_tf32(kv.z); kd[3] = to_tf32(kv.w);
            vd[0] = to_tf32(vv.x); vd[1] = to_tf32(vv.y);
            vd[2] = to_tf32(vv.z); vd[3] = to_tf32(vv.w);
        }
        __syncthreads();

        // --- S = Q K^T (this warp's 16 rows x all 64 keys) ---
        float sc[8][4];
#pragma unroll
        for (int nt = 0; nt < 8; nt++)
#pragma unroll
            for (int r = 0; r < 4; r++) sc[nt][r] = 0.f;

#pragma unroll
        for (int kk = 0; kk < 64; kk += 8) {
            const int mr = w * 16 + grp;
            uint32_t a0 = Qs[(mr    ) * QK_PAD + kk + tig    ];
            uint32_t a1 = Qs[(mr + 8) * QK_PAD + kk + tig    ];
            uint32_t a2 = Qs[(mr    ) * QK_PAD + kk + tig + 4];
            uint32_t a3 = Qs[(mr + 8) * QK_PAD + kk + tig + 4];
#pragma unroll
            for (int nt = 0; nt < 8; nt++) {
                uint32_t b0 = Ks[(nt * 8 + grp) * QK_PAD + kk + tig    ];
                uint32_t b1 = Ks[(nt * 8 + grp) * QK_PAD + kk + tig + 4];
                mma_tf32(sc[nt], a0, a1, a2, a3, b0, b1);
            }
        }

        // --- scale + mask + online softmax ---
        const bool diag = (kt == qt);
        float mx0 = -3.0e38f, mx1 = -3.0e38f;
#pragma unroll
        for (int nt = 0; nt < 8; nt++) {
            int cg = kt * 64 + nt * 8 + 2 * tig;   // global col of sc[nt][0]
            float s0 = sc[nt][0] * frs0;
            float s1 = sc[nt][1] * frs0;
            float s2 = sc[nt][2] * frs1;
            float s3 = sc[nt][3] * frs1;
            if (diag) {
                if (cg     >= rg0)     s0 = -1e30f;
                if (cg + 1 >= rg0)     s1 = -1e30f;
                if (cg     >= rg0 + 8) s2 = -1e30f;
                if (cg + 1 >= rg0 + 8) s3 = -1e30f;
            }
            sc[nt][0] = s0; sc[nt][1] = s1; sc[nt][2] = s2; sc[nt][3] = s3;
            mx0 = fmaxf(mx0, fmaxf(s0, s1));
            mx1 = fmaxf(mx1, fmaxf(s2, s3));
        }
        mx0 = fmaxf(mx0, __shfl_xor_sync(0xffffffffu, mx0, 1));
        mx0 = fmaxf(mx0, __shfl_xor_sync(0xffffffffu, mx0, 2));
        mx1 = fmaxf(mx1, __shfl_xor_sync(0xffffffffu, mx1, 1));
        mx1 = fmaxf(mx1, __shfl_xor_sync(0xffffffffu, mx1, 2));

        float mn0 = fmaxf(m0, mx0);
        float mn1 = fmaxf(m1, mx1);
        float al0 = __expf(m0 - mn0);
        float al1 = __expf(m1 - mn1);
        m0 = mn0; m1 = mn1;

        float su0 = 0.f, su1 = 0.f;
        uint32_t pu[8][4];
#pragma unroll
        for (int nt = 0; nt < 8; nt++) {
            float p0 = __expf(sc[nt][0] - mn0);
            float p1 = __expf(sc[nt][1] - mn0);
            float p2 = __expf(sc[nt][2] - mn1);
            float p3 = __expf(sc[nt][3] - mn1);
            su0 += p0 + p1;
            su1 += p2 + p3;
            pu[nt][0] = to_tf32(p0); pu[nt][1] = to_tf32(p1);
            pu[nt][2] = to_tf32(p2); pu[nt][3] = to_tf32(p3);
        }
        su0 += __shfl_xor_sync(0xffffffffu, su0, 1);
        su0 += __shfl_xor_sync(0xffffffffu, su0, 2);
        su1 += __shfl_xor_sync(0xffffffffu, su1, 1);
        su1 += __shfl_xor_sync(0xffffffffu, su1, 2);
        l0 = l0 * al0 + su0;
        l1 = l1 * al1 + su1;
#pragma unroll
        for (int nt = 0; nt < 8; nt++) {
            o[nt][0] *= al0; o[nt][1] *= al0;
            o[nt][2] *= al1; o[nt][3] *= al1;
        }

        // --- O += P V : shuffle C-frag layout (cols 2*tig) -> A-frag (cols tig/tig+4)
        const int srcbase = (lane & ~3) | (tig >> 1);
        const int odd = tig & 1;
#pragma unroll
        for (int j = 0; j < 8; j++) {
            uint32_t x0a = __shfl_sync(0xffffffffu, pu[j][0], srcbase);
            uint32_t x1a = __shfl_sync(0xffffffffu, pu[j][1], srcbase);
            uint32_t x2a = __shfl_sync(0xffffffffu, pu[j][2], srcbase);
            uint32_t x3a = __shfl_sync(0xffffffffu, pu[j][3], srcbase);
            uint32_t x0b = __shfl_sync(0xffffffffu, pu[j][0], srcbase + 2);
            uint32_t x1b = __shfl_sync(0xffffffffu, pu[j][1], srcbase + 2);
            uint32_t x2b = __shfl_sync(0xffffffffu, pu[j][2], srcbase + 2);
            uint32_t x3b = __shfl_sync(0xffffffffu, pu[j][3], srcbase + 2);
            uint32_t a0 = odd ? x1a : x0a;   // (row grp,   key 8j+tig)
            uint32_t a1 = odd ? x3a : x2a;   // (row grp+8, key 8j+tig)
            uint32_t a2 = odd ? x1b : x0b;   // (row grp,   key 8j+tig+4)
            uint32_t a3 = odd ? x3b : x2b;   // (row grp+8, key 8j+tig+4)
#pragma unroll
            for (int nt = 0; nt < 8; nt++) {
                uint32_t b0 = Vs[(j * 8 + tig    ) * V_PAD + nt * 8 + grp];
                uint32_t b1 = Vs[(j * 8 + tig + 4) * V_PAD + nt * 8 + grp];
                mma_tf32(o[nt], a0, a1, a2, a3, b0, b1);
            }
        }
    }

    // Epilogue: normalize, zero row 0, write float2 pairs
    float inv0 = (rg0 == 0) ? 0.f : (1.0f / l0);
    float inv1 = 1.0f / l1;
#pragma unroll
    for (int nt = 0; nt < 8; nt++) {
        int col = nt * 8 + tig * 2;
        *(float2*)(Out + base + (size_t)(rg0    ) * DD + col) =
            make_float2(o[nt][0] * inv0, o[nt][1] * inv0);
        *(float2*)(Out + base + (size_t)(rg0 + 8) * DD + col) =
            make_float2(o[nt][2] * inv1, o[nt][3] * inv1);
    }
}

// ---------------------------------------------------------------------------
// out[row] = LayerNorm(x[row] + r[row]) * g + be       (D = 512, 128 threads)
// ---------------------------------------------------------------------------
__global__ void __launch_bounds__(128) ln_res_kernel(
    const float* __restrict__ x, const float* __restrict__ r,
    const float* __restrict__ g, const float* __restrict__ be,
    float* __restrict__ out)
{
    int row = blockIdx.x;
    int tid = threadIdx.x;
    const float4* xp = (const float4*)(x + (size_t)row * DD);
    const float4* rp = (const float4*)(r + (size_t)row * DD);
    float4 v = xp[tid], w = rp[tid];
    v.x += w.x; v.y += w.y; v.z += w.z; v.w += w.w;
    float s  = v.x + v.y + v.z + v.w;
    float ss = v.x * v.x + v.y * v.y + v.z * v.z + v.w * v.w;
#pragma unroll
    for (int ofs = 16; ofs > 0; ofs >>= 1) {
        s  += __shfl_xor_sync(0xffffffffu, s,  ofs);
        ss += __shfl_xor_sync(0xffffffffu, ss, ofs);
    }
    __shared__ float sb[4], ssb[4];
    int wid = tid >> 5;
    if ((tid & 31) == 0) { sb[wid] = s; ssb[wid] = ss; }
    __syncthreads();
    s  = sb[0]  + sb[1]  + sb[2]  + sb[3];
    ss = ssb[0] + ssb[1] + ssb[2] + ssb[3];
    float mean = s * (1.0f / DD);
    float var  = ss * (1.0f / DD) - mean * mean;
    float rs   = rsqrtf(var + 1e-5f);
    float4 gv = ((const float4*)g)[tid];
    float4 bv = ((const float4*)be)[tid];
    float4 o4;
    o4.x = (v.x - mean) * rs * gv.x + bv.x;
    o4.y = (v.y - mean) * rs * gv.y + bv.y;
    o4.z = (v.z - mean) * rs * gv.z + bv.z;
    o4.w = (v.w - mean) * rs * gv.w + bv.w;
    ((float4*)(out + (size_t)row * DD))[tid] = o4;
}

// ---------------------------------------------------------------------------
extern "C" void kernel_launch(void* const* d_in, const int* in_sizes, int n_in,
                              void* d_out, int out_size)
{
    const float* qe  = (const float*)d_in[0];
    const float* qa  = (const float*)d_in[1];
    const float* fr  = (const float*)d_in[2];
    const float* pe  = (const float*)d_in[3];
    const float* Wk  = (const float*)d_in[4];
    const float* bk  = (const float*)d_in[5];
    const float* Wv  = (const float*)d_in[6];
    const float* bv  = (const float*)d_in[7];
    const float* Wo  = (const float*)d_in[8];
    const float* bo  = (const float*)d_in[9];
    const float* g1  = (const float*)d_in[10];
    const float* be1 = (const float*)d_in[11];
    const float* W1  = (const float*)d_in[12];
    const float* bf1 = (const float*)d_in[13];
    const float* W2  = (const float*)d_in[14];
    const float* bf2 = (const float*)d_in[15];
    const float* g2  = (const float*)d_in[16];
    const float* be2 = (const float*)d_in[17];
    float* out = (float*)d_out;

    float *px, *py, *pq, *pv, *pt, *pff;
    cudaGetSymbolAddress((void**)&px,  g_x);
    cudaGetSymbolAddress((void**)&py,  g_y);
    cudaGetSymbolAddress((void**)&pq,  g_q);
    cudaGetSymbolAddress((void**)&pv,  g_v);
    cudaGetSymbolAddress((void**)&pt,  g_t);
    cudaGetSymbolAddress((void**)&pff, g_ff);

    cudaFuncSetAttribute(attn_mma_kernel,
                         cudaFuncAttributeMaxDynamicSharedMemorySize,
                         (int)ATTN_SMEM);

    add_pe_kernel<<<(BSD / 4 + 255) / 256, 256>>>(
        (const float4*)qe, (const float4*)qa, (const float4*)pe,
        (float4*)px, (float4*)py);

    dim3 g512(DD / 128, MTOK / 128);    // (4, 128)
    dim3 gff(FFD / 128, MTOK / 128);    // (16, 128)
    dim3 gattn(SS / 64, BB * HH);       // (8, 256)

    for (int i = 0; i < NBLK; i++) {
        const float* Wki = Wk + (size_t)i * DD * DD;
        const float* Wvi = Wv + (size_t)i * DD * DD;
        const float* Woi = Wo + (size_t)i * DD * DD;
        const float* W1i = W1 + (size_t)i * DD * FFD;
        const float* W2i = W2 + (size_t)i * FFD * DD;

        tf32_gemm_kernel<false><<<g512, 256>>>(px, Wki, bk + i * DD, pq, MTOK, DD, DD);
        tf32_gemm_kernel<false><<<g512, 256>>>(py, Wvi, bv + i * DD, pv, MTOK, DD, DD);
        attn_mma_kernel<<<gattn, 128, ATTN_SMEM>>>(pq, pv, fr, pt);
        tf32_gemm_kernel<false><<<g512, 256>>>(pt, Woi, bo + i * DD, pq, MTOK, DD, DD);
        ln_res_kernel<<<MTOK, 128>>>(px, pq, g1 + i * DD, be1 + i * DD, px);
        tf32_gemm_kernel<true><<<gff, 256>>>(px, W1i, bf1 + i * FFD, pff, MTOK, FFD, DD);
        tf32_gemm_kernel<false><<<g512, 256>>>(pff, W2i, bf2 + i * DD, pt, MTOK, DD, FFD);
        float* dst = (i == NBLK - 1) ? out : px;
        ln_res_kernel<<<MTOK, 128>>>(px, pt, g2 + i * DD, be2 + i * DD, dst);
    }
}

// round 6
// speedup vs baseline: 3.1478x; 1.1935x over previous
#include <cuda_runtime.h>
#include <math.h>
#include <stdint.h>

// Problem constants
#define BB   32
#define SS   512
#define DD   512
#define HH   8
#define DKK  64
#define FFD  2048
#define NBLK 2
#define MTOK (BB*SS)            // 16384 token rows
#define BSD  (BB*SS*DD)         // 8388608
#define BSF  (BB*SS*FFD)        // 33554432

// Scratch (static device globals — no allocation allowed)
__device__ float g_x[BSD];
__device__ float g_y[BSD];
__device__ float g_q[BSD];
__device__ float g_v[BSD];
__device__ float g_t[BSD];
__device__ float g_ff[BSF];

// ---------------------------------------------------------------------------
__global__ void add_pe_kernel(const float4* __restrict__ qe,
                              const float4* __restrict__ qa,
                              const float4* __restrict__ pe,
                              float4* __restrict__ x,
                              float4* __restrict__ y)
{
    int i = blockIdx.x * blockDim.x + threadIdx.x;
    const int n4 = BSD / 4;
    if (i >= n4) return;
    int pi = i & (SS * DD / 4 - 1);
    float4 p = pe[pi];
    float4 a = qe[i];
    a.x += p.x; a.y += p.y; a.z += p.z; a.w += p.w;
    x[i] = a;
    float4 b = qa[i];
    b.x += p.x; b.y += p.y; b.z += p.z; b.w += p.w;
    y[i] = b;
}

// ---------------------------------------------------------------------------
// TF32 helpers
// ---------------------------------------------------------------------------
__device__ __forceinline__ uint32_t to_tf32(float x) {
    uint32_t y;
    asm("cvt.rna.tf32.f32 %0, %1;" : "=r"(y) : "f"(x));
    return y;
}

__device__ __forceinline__ void mma_tf32(float c[4],
                                         uint32_t a0, uint32_t a1,
                                         uint32_t a2, uint32_t a3,
                                         uint32_t b0, uint32_t b1)
{
    asm volatile(
        "mma.sync.aligned.m16n8k8.row.col.f32.tf32.tf32.f32 "
        "{%0,%1,%2,%3}, {%4,%5,%6,%7}, {%8,%9}, {%0,%1,%2,%3};"
        : "+f"(c[0]), "+f"(c[1]), "+f"(c[2]), "+f"(c[3])
        : "r"(a0), "r"(a1), "r"(a2), "r"(a3), "r"(b0), "r"(b1));
}

__device__ __forceinline__ void cp_async16(uint32_t smem_addr, const void* gptr) {
    asm volatile("cp.async.cg.shared.global [%0], [%1], 16;"
                 :: "r"(smem_addr), "l"(gptr));
}
__device__ __forceinline__ void cp_commit() {
    asm volatile("cp.async.commit_group;");
}
template<int N>
__device__ __forceinline__ void cp_wait() {
    asm volatile("cp.async.wait_group %0;" :: "n"(N));
}

// ---------------------------------------------------------------------------
// Pipelined TF32 GEMM: C[M,N] = A[M,K] @ W[K,N] + bias[N]  (optional ReLU)
// 128x128 tile, BK=32, 256 threads (8 warps: 2x4, 64x32 warp tiles),
// 2-stage cp.async double buffer. Operands fed to mma as raw fp32 bits
// (HW tf32 truncation) — no cvt in the load path.
// As: [2][128][36] row-major  (frag addr 4*grp+tig mod 32 -> conflict-free)
// Bs: [2][32][136]            (frag addr 8*tig+grp mod 32 -> conflict-free)
// ---------------------------------------------------------------------------
#define AST 36
#define BST 136
#define ASZ (128 * AST)
#define BSZ (32 * BST)
#define GEMM_SMEM ((2 * ASZ + 2 * BSZ) * sizeof(float))

template<bool RELU>
__global__ void __launch_bounds__(256, 2) tf32_gemm_pipe(
    const float* __restrict__ A, const float* __restrict__ W,
    const float* __restrict__ bias, float* __restrict__ C,
    int M, int N, int K)
{
    extern __shared__ float smf[];
    float* Asm = smf;                 // [2][128][AST]
    float* Bsm = smf + 2 * ASZ;       // [2][32][BST]

    const int tid   = threadIdx.x;
    const int lane  = tid & 31;
    const int wid   = tid >> 5;
    const int wm    = wid & 1;
    const int wn    = wid >> 1;
    const int grp   = lane >> 2;
    const int tig   = lane & 3;
    const int m0    = blockIdx.y * 128;
    const int n0    = blockIdx.x * 128;

    const uint32_t sA = (uint32_t)__cvta_generic_to_shared(Asm);
    const uint32_t sB = (uint32_t)__cvta_generic_to_shared(Bsm);

    // per-thread load coords
    const int a_row = tid >> 1;            // 0..127
    const int a_c0  = (tid & 1) * 16;      // 0 or 16 (float offset, covers 16 floats)
    const int b_row = tid >> 5;            // 0..7 base (4 iters of +8)
    const int b_c4  = lane * 4;            // 0..124

    float acc[4][4][4];
#pragma unroll
    for (int i = 0; i < 4; i++)
#pragma unroll
        for (int j = 0; j < 4; j++)
#pragma unroll
            for (int r = 0; r < 4; r++) acc[i][j][r] = 0.f;

    const int nk = K >> 5;

    // ---- stage loader ----
    auto load_stage = [&](int stg, int k0) {
        // A: 128 rows x 32 floats = 1024 x 16B chunks -> 4 per thread
        {
            const float* g0 = A + (size_t)(m0 + a_row) * K + k0 + a_c0;
            uint32_t d0 = sA + (uint32_t)((stg * ASZ + a_row * AST + a_c0) * 4);
            cp_async16(d0,      g0);
            cp_async16(d0 + 16, g0 + 4);
            cp_async16(d0 + 32, g0 + 8);
            cp_async16(d0 + 48, g0 + 12);
        }
        // B: 32 rows x 128 floats = 1024 x 16B chunks -> 4 per thread
#pragma unroll
        for (int it = 0; it < 4; it++) {
            int row = b_row + it * 8;
            const float* g0 = W + (size_t)(k0 + row) * N + n0 + b_c4;
            uint32_t d0 = sB + (uint32_t)((stg * BSZ + row * BST + b_c4) * 4);
            cp_async16(d0, g0);
        }
    };

    load_stage(0, 0);
    cp_commit();

    for (int kt = 0; kt < nk; kt++) {
        if (kt + 1 < nk) load_stage((kt + 1) & 1, (kt + 1) * 32);
        cp_commit();
        cp_wait<1>();
        __syncthreads();

        const float* pA = Asm + (kt & 1) * ASZ;
        const float* pB = Bsm + (kt & 1) * BSZ;

#pragma unroll
        for (int kk = 0; kk < 32; kk += 8) {
            uint32_t af[4][4];
            uint32_t bf[4][2];
#pragma unroll
            for (int mt = 0; mt < 4; mt++) {
                int mr = wm * 64 + mt * 16 + grp;
                af[mt][0] = __float_as_uint(pA[(mr    ) * AST + kk + tig    ]);
                af[mt][1] = __float_as_uint(pA[(mr + 8) * AST + kk + tig    ]);
                af[mt][2] = __float_as_uint(pA[(mr    ) * AST + kk + tig + 4]);
                af[mt][3] = __float_as_uint(pA[(mr + 8) * AST + kk + tig + 4]);
            }
#pragma unroll
            for (int nt = 0; nt < 4; nt++) {
                int nc = wn * 32 + nt * 8 + grp;
                bf[nt][0] = __float_as_uint(pB[(kk + tig    ) * BST + nc]);
                bf[nt][1] = __float_as_uint(pB[(kk + tig + 4) * BST + nc]);
            }
#pragma unroll
            for (int mt = 0; mt < 4; mt++)
#pragma unroll
                for (int nt = 0; nt < 4; nt++)
                    mma_tf32(acc[mt][nt],
                             af[mt][0], af[mt][1], af[mt][2], af[mt][3],
                             bf[nt][0], bf[nt][1]);
        }
        __syncthreads();
    }

    // Epilogue: bias (+ReLU), write float2 pairs
#pragma unroll
    for (int mt = 0; mt < 4; mt++) {
#pragma unroll
        for (int nt = 0; nt < 4; nt++) {
            int row = m0 + wm * 64 + mt * 16 + grp;
            int col = n0 + wn * 32 + nt * 8 + tig * 2;
            float b0 = bias[col], b1 = bias[col + 1];
            float v0 = acc[mt][nt][0] + b0;
            float v1 = acc[mt][nt][1] + b1;
            float v2 = acc[mt][nt][2] + b0;
            float v3 = acc[mt][nt][3] + b1;
            if (RELU) {
                v0 = fmaxf(v0, 0.f); v1 = fmaxf(v1, 0.f);
                v2 = fmaxf(v2, 0.f); v3 = fmaxf(v3, 0.f);
            }
            *(float2*)(C + (size_t)row * N + col)       = make_float2(v0, v1);
            *(float2*)(C + (size_t)(row + 8) * N + col) = make_float2(v2, v3);
        }
    }
}

// ---------------------------------------------------------------------------
// TF32 tensor-core flash attention (unchanged from R4 — known good).
// ---------------------------------------------------------------------------
#define QK_PAD 68
#define V_PAD  72
#define ATTN_SMEM ((2 * 64 * QK_PAD + 64 * V_PAD) * sizeof(uint32_t))

__global__ void __launch_bounds__(128, 4) attn_mma_kernel(
    const float* __restrict__ Q, const float* __restrict__ V,
    const float* __restrict__ FR, float* __restrict__ Out)
{
    extern __shared__ uint32_t smu[];
    uint32_t* Qs = smu;                      // [64][QK_PAD]
    uint32_t* Ks = smu + 64 * QK_PAD;        // [64][QK_PAD]
    uint32_t* Vs = smu + 2 * 64 * QK_PAD;    // [64][V_PAD]

    const int qt   = blockIdx.x;
    const int bh   = blockIdx.y;
    const int b    = bh >> 3;
    const int h    = bh & 7;
    const int tid  = threadIdx.x;
    const int lane = tid & 31;
    const int w    = tid >> 5;
    const int grp  = lane >> 2;
    const int tig  = lane & 3;
    const int q0   = qt * 64;
    const size_t base = (size_t)b * SS * DD + (size_t)h * DKK;

#pragma unroll
    for (int j = 0; j < 8; j++) {
        int idx = j * 128 + tid;
        int r   = idx >> 4;
        int c4  = (idx & 15) * 4;
        float4 v = *(const float4*)(Q + base + (size_t)(q0 + r) * DD + c4);
        uint32_t* d = Qs + r * QK_PAD + c4;
        d[0] = to_tf32(v.x); d[1] = to_tf32(v.y);
        d[2] = to_tf32(v.z); d[3] = to_tf32(v.w);
    }

    const int rg0 = q0 + w * 16 + grp;
    const float frs0 = FR[b * SS + rg0]     * 0.125f;
    const float frs1 = FR[b * SS + rg0 + 8] * 0.125f;

    float m0 = -3.0e38f, m1 = -3.0e38f, l0 = 0.f, l1 = 0.f;
    float o[8][4];
#pragma unroll
    for (int nt = 0; nt < 8; nt++)
#pragma unroll
        for (int r = 0; r < 4; r++) o[nt][r] = 0.f;

    for (int kt = 0; kt <= qt; kt++) {
        __syncthreads();
#pragma unroll
        for (int j = 0; j < 8; j++) {
            int idx = j * 128 + tid;
            int r   = idx >> 4;
            int c4  = (idx & 15) * 4;
            const float* gk = Q + base + (size_t)(kt * 64 + r) * DD + c4;
            const float* gv = V + base + (size_t)(kt * 64 + r) * DD + c4;
            float4 kv = *(const float4*)gk;
            float4 vv = *(const float4*)gv;
            uint32_t* kd = Ks + r * QK_PAD + c4;
            uint32_t* vd = Vs + r * V_PAD  + c4;
            kd[0] = to_tf32(kv.x); kd[1] = to_tf32(kv.y);
            kd[2] = to_tf32(kv.z); kd[3] = to_tf32(kv.w);
            vd[0] = to_tf32(vv.x); vd[1] = to_tf32(vv.y);
            vd[2] = to_tf32(vv.z); vd[3] = to_tf32(vv.w);
        }
        __syncthreads();

        float sc[8][4];
#pragma unroll
        for (int nt = 0; nt < 8; nt++)
#pragma unroll
            for (int r = 0; r < 4; r++) sc[nt][r] = 0.f;

#pragma unroll
        for (int kk = 0; kk < 64; kk += 8) {
            const int mr = w * 16 + grp;
            uint32_t a0 = Qs[(mr    ) * QK_PAD + kk + tig    ];
            uint32_t a1 = Qs[(mr + 8) * QK_PAD + kk + tig    ];
            uint32_t a2 = Qs[(mr    ) * QK_PAD + kk + tig + 4];
            uint32_t a3 = Qs[(mr + 8) * QK_PAD + kk + tig + 4];
#pragma unroll
            for (int nt = 0; nt < 8; nt++) {
                uint32_t b0 = Ks[(nt * 8 + grp) * QK_PAD + kk + tig    ];
                uint32_t b1 = Ks[(nt * 8 + grp) * QK_PAD + kk + tig + 4];
                mma_tf32(sc[nt], a0, a1, a2, a3, b0, b1);
            }
        }

        const bool diag = (kt == qt);
        float mx0 = -3.0e38f, mx1 = -3.0e38f;
#pragma unroll
        for (int nt = 0; nt < 8; nt++) {
            int cg = kt * 64 + nt * 8 + 2 * tig;
            float s0 = sc[nt][0] * frs0;
            float s1 = sc[nt][1] * frs0;
            float s2 = sc[nt][2] * frs1;
            float s3 = sc[nt][3] * frs1;
            if (diag) {
                if (cg     >= rg0)     s0 = -1e30f;
                if (cg + 1 >= rg0)     s1 = -1e30f;
                if (cg     >= rg0 + 8) s2 = -1e30f;
                if (cg + 1 >= rg0 + 8) s3 = -1e30f;
            }
            sc[nt][0] = s0; sc[nt][1] = s1; sc[nt][2] = s2; sc[nt][3] = s3;
            mx0 = fmaxf(mx0, fmaxf(s0, s1));
            mx1 = fmaxf(mx1, fmaxf(s2, s3));
        }
        mx0 = fmaxf(mx0, __shfl_xor_sync(0xffffffffu, mx0, 1));
        mx0 = fmaxf(mx0, __shfl_xor_sync(0xffffffffu, mx0, 2));
        mx1 = fmaxf(mx1, __shfl_xor_sync(0xffffffffu, mx1, 1));
        mx1 = fmaxf(mx1, __shfl_xor_sync(0xffffffffu, mx1, 2));

        float mn0 = fmaxf(m0, mx0);
        float mn1 = fmaxf(m1, mx1);
        float al0 = __expf(m0 - mn0);
        float al1 = __expf(m1 - mn1);
        m0 = mn0; m1 = mn1;

        float su0 = 0.f, su1 = 0.f;
        uint32_t pu[8][4];
#pragma unroll
        for (int nt = 0; nt < 8; nt++) {
            float p0 = __expf(sc[nt][0] - mn0);
            float p1 = __expf(sc[nt][1] - mn0);
            float p2 = __expf(sc[nt][2] - mn1);
            float p3 = __expf(sc[nt][3] - mn1);
            su0 += p0 + p1;
            su1 += p2 + p3;
            pu[nt][0] = to_tf32(p0); pu[nt][1] = to_tf32(p1);
            pu[nt][2] = to_tf32(p2); pu[nt][3] = to_tf32(p3);
        }
        su0 += __shfl_xor_sync(0xffffffffu, su0, 1);
        su0 += __shfl_xor_sync(0xffffffffu, su0, 2);
        su1 += __shfl_xor_sync(0xffffffffu, su1, 1);
        su1 += __shfl_xor_sync(0xffffffffu, su1, 2);
        l0 = l0 * al0 + su0;
        l1 = l1 * al1 + su1;
#pragma unroll
        for (int nt = 0; nt < 8; nt++) {
            o[nt][0] *= al0; o[nt][1] *= al0;
            o[nt][2] *= al1; o[nt][3] *= al1;
        }

        const int srcbase = (lane & ~3) | (tig >> 1);
        const int odd = tig & 1;
#pragma unroll
        for (int j = 0; j < 8; j++) {
            uint32_t x0a = __shfl_sync(0xffffffffu, pu[j][0], srcbase);
            uint32_t x1a = __shfl_sync(0xffffffffu, pu[j][1], srcbase);
            uint32_t x2a = __shfl_sync(0xffffffffu, pu[j][2], srcbase);
            uint32_t x3a = __shfl_sync(0xffffffffu, pu[j][3], srcbase);
            uint32_t x0b = __shfl_sync(0xffffffffu, pu[j][0], srcbase + 2);
            uint32_t x1b = __shfl_sync(0xffffffffu, pu[j][1], srcbase + 2);
            uint32_t x2b = __shfl_sync(0xffffffffu, pu[j][2], srcbase + 2);
            uint32_t x3b = __shfl_sync(0xffffffffu, pu[j][3], srcbase + 2);
            uint32_t a0 = odd ? x1a : x0a;
            uint32_t a1 = odd ? x3a : x2a;
            uint32_t a2 = odd ? x1b : x0b;
            uint32_t a3 = odd ? x3b : x2b;
#pragma unroll
            for (int nt = 0; nt < 8; nt++) {
                uint32_t b0 = Vs[(j * 8 + tig    ) * V_PAD + nt * 8 + grp];
                uint32_t b1 = Vs[(j * 8 + tig + 4) * V_PAD + nt * 8 + grp];
                mma_tf32(o[nt], a0, a1, a2, a3, b0, b1);
            }
        }
    }

    float inv0 = (rg0 == 0) ? 0.f : (1.0f / l0);
    float inv1 = 1.0f / l1;
#pragma unroll
    for (int nt = 0; nt < 8; nt++) {
        int col = nt * 8 + tig * 2;
        *(float2*)(Out + base + (size_t)(rg0    ) * DD + col) =
            make_float2(o[nt][0] * inv0, o[nt][1] * inv0);
        *(float2*)(Out + base + (size_t)(rg0 + 8) * DD + col) =
            make_float2(o[nt][2] * inv1, o[nt][3] * inv1);
    }
}

// ---------------------------------------------------------------------------
// out[row] = LayerNorm(x[row] + r[row]) * g + be       (D = 512, 128 threads)
// ---------------------------------------------------------------------------
__global__ void __launch_bounds__(128) ln_res_kernel(
    const float* __restrict__ x, const float* __restrict__ r,
    const float* __restrict__ g, const float* __restrict__ be,
    float* __restrict__ out)
{
    int row = blockIdx.x;
    int tid = threadIdx.x;
    const float4* xp = (const float4*)(x + (size_t)row * DD);
    const float4* rp = (const float4*)(r + (size_t)row * DD);
    float4 v = xp[tid], w = rp[tid];
    v.x += w.x; v.y += w.y; v.z += w.z; v.w += w.w;
    float s  = v.x + v.y + v.z + v.w;
    float ss = v.x * v.x + v.y * v.y + v.z * v.z + v.w * v.w;
#pragma unroll
    for (int ofs = 16; ofs > 0; ofs >>= 1) {
        s  += __shfl_xor_sync(0xffffffffu, s,  ofs);
        ss += __shfl_xor_sync(0xffffffffu, ss, ofs);
    }
    __shared__ float sb[4], ssb[4];
    int wid = tid >> 5;
    if ((tid & 31) == 0) { sb[wid] = s; ssb[wid] = ss; }
    __syncthreads();
    s  = sb[0]  + sb[1]  + sb[2]  + sb[3];
    ss = ssb[0] + ssb[1] + ssb[2] + ssb[3];
    float mean = s * (1.0f / DD);
    float var  = ss * (1.0f / DD) - mean * mean;
    float rs   = rsqrtf(var + 1e-5f);
    float4 gv = ((const float4*)g)[tid];
    float4 bv = ((const float4*)be)[tid];
    float4 o4;
    o4.x = (v.x - mean) * rs * gv.x + bv.x;
    o4.y = (v.y - mean) * rs * gv.y + bv.y;
    o4.z = (v.z - mean) * rs * gv.z + bv.z;
    o4.w = (v.w - mean) * rs * gv.w + bv.w;
    ((float4*)(out + (size_t)row * DD))[tid] = o4;
}

// ---------------------------------------------------------------------------
extern "C" void kernel_launch(void* const* d_in, const int* in_sizes, int n_in,
                              void* d_out, int out_size)
{
    const float* qe  = (const float*)d_in[0];
    const float* qa  = (const float*)d_in[1];
    const float* fr  = (const float*)d_in[2];
    const float* pe  = (const float*)d_in[3];
    const float* Wk  = (const float*)d_in[4];
    const float* bk  = (const float*)d_in[5];
    const float* Wv  = (const float*)d_in[6];
    const float* bv  = (const float*)d_in[7];
    const float* Wo  = (const float*)d_in[8];
    const float* bo  = (const float*)d_in[9];
    const float* g1  = (const float*)d_in[10];
    const float* be1 = (const float*)d_in[11];
    const float* W1  = (const float*)d_in[12];
    const float* bf1 = (const float*)d_in[13];
    const float* W2  = (const float*)d_in[14];
    const float* bf2 = (const float*)d_in[15];
    const float* g2  = (const float*)d_in[16];
    const float* be2 = (const float*)d_in[17];
    float* out = (float*)d_out;

    float *px, *py, *pq, *pv, *pt, *pff;
    cudaGetSymbolAddress((void**)&px,  g_x);
    cudaGetSymbolAddress((void**)&py,  g_y);
    cudaGetSymbolAddress((void**)&pq,  g_q);
    cudaGetSymbolAddress((void**)&pv,  g_v);
    cudaGetSymbolAddress((void**)&pt,  g_t);
    cudaGetSymbolAddress((void**)&pff, g_ff);

    cudaFuncSetAttribute(attn_mma_kernel,
                         cudaFuncAttributeMaxDynamicSharedMemorySize,
                         (int)ATTN_SMEM);
    cudaFuncSetAttribute(tf32_gemm_pipe<false>,
                         cudaFuncAttributeMaxDynamicSharedMemorySize,
                         (int)GEMM_SMEM);
    cudaFuncSetAttribute(tf32_gemm_pipe<true>,
                         cudaFuncAttributeMaxDynamicSharedMemorySize,
                         (int)GEMM_SMEM);

    add_pe_kernel<<<(BSD / 4 + 255) / 256, 256>>>(
        (const float4*)qe, (const float4*)qa, (const float4*)pe,
        (float4*)px, (float4*)py);

    dim3 g512(DD / 128, MTOK / 128);    // (4, 128)
    dim3 gff(FFD / 128, MTOK / 128);    // (16, 128)
    dim3 gattn(SS / 64, BB * HH);       // (8, 256)

    for (int i = 0; i < NBLK; i++) {
        const float* Wki = Wk + (size_t)i * DD * DD;
        const float* Wvi = Wv + (size_t)i * DD * DD;
        const float* Woi = Wo + (size_t)i * DD * DD;
        const float* W1i = W1 + (size_t)i * DD * FFD;
        const float* W2i = W2 + (size_t)i * FFD * DD;

        tf32_gemm_pipe<false><<<g512, 256, GEMM_SMEM>>>(px, Wki, bk + i * DD, pq, MTOK, DD, DD);
        tf32_gemm_pipe<false><<<g512, 256, GEMM_SMEM>>>(py, Wvi, bv + i * DD, pv, MTOK, DD, DD);
        attn_mma_kernel<<<gattn, 128, ATTN_SMEM>>>(pq, pv, fr, pt);
        tf32_gemm_pipe<false><<<g512, 256, GEMM_SMEM>>>(pt, Woi, bo + i * DD, pq, MTOK, DD, DD);
        ln_res_kernel<<<MTOK, 128>>>(px, pq, g1 + i * DD, be1 + i * DD, px);
        tf32_gemm_pipe<true><<<gff, 256, GEMM_SMEM>>>(px, W1i, bf1 + i * FFD, pff, MTOK, FFD, DD);
        tf32_gemm_pipe<false><<<g512, 256, GEMM_SMEM>>>(pff, W2i, bf2 + i * DD, pt, MTOK, DD, FFD);
        float* dst = (i == NBLK - 1) ? out : px;
        ln_res_kernel<<<MTOK, 128>>>(px, pt, g2 + i * DD, be2 + i * DD, dst);
    }
}